// round 4
// baseline (speedup 1.0000x reference)
#include <cuda_runtime.h>
#include <math.h>

// ExponentialUnitNorm, single-pass decoupled-lookback scan.
// y = x / sqrt(s_t), s_t = 0.01*|x_t| + 0.99*s_{t-1}
// x [B=16, T=2000, F=481, 2] f32; init_state [F] f32.
//
// Chunked affine recurrence: s_end(chunk) = P + alpha^L * s_in.
// Each block owns (b, c): L=16 timesteps held entirely in registers across
// the lookback wait, so x is read from DRAM exactly once. Total DRAM traffic
// = read x (123MB) + write y (123MB) = 246MB (was 369MB in 3-pass version).

namespace {
constexpr int B  = 16;
constexpr int T  = 2000;
constexpr int Fq = 481;
constexpr int L  = 16;           // timesteps per chunk (register resident)
constexpr int NC = T / L;        // 125 chunks
constexpr float AL   = 0.99f;
constexpr float OMA  = 0.01f;
constexpr float EPSC = 1e-14f;
}

__device__ float g_agg [B * NC * Fq];   // chunk aggregates (recurrence from 0)
__device__ float g_pref[B * NC * Fq];   // inclusive prefix (state at chunk end)
__device__ int   g_flag[B * NC];        // 0 = none, 1 = aggregate, 2 = prefix

__global__ __launch_bounds__(512, 2) void k_scan(const float* __restrict__ x,
                                                 const float* __restrict__ init_state,
                                                 float* __restrict__ y,
                                                 float aLL) {
    const int bid = blockIdx.x;          // bid = c*B + b (chunk-major)
    const int c   = bid / B;
    const int b   = bid - c * B;
    const int f   = threadIdx.x;
    const bool act = (f < Fq);
    const int lane = threadIdx.x & 31;

    const size_t base = (size_t)(b * T + c * L) * Fq + f;

    // ---- load chunk into registers, compute aggregate ----
    float2 v[L];
    float p = 0.0f;
    if (act) {
        const float2* xp = reinterpret_cast<const float2*>(x) + base;
        #pragma unroll
        for (int j = 0; j < L; ++j) v[j] = xp[(size_t)j * Fq];
        #pragma unroll
        for (int j = 0; j < L; ++j) {
            float r2 = fmaxf(fmaf(v[j].x, v[j].x, v[j].y * v[j].y), EPSC);
            p = fmaf(r2 * rsqrtf(r2), OMA, p * AL);
        }
    }

    const size_t row = (size_t)bid * Fq;
    float s_in = 0.0f;

    if (c == 0) {
        // incoming state is init_state; publish prefix directly
        if (act) {
            s_in = init_state[f];
            g_pref[row + f] = fmaf(aLL, s_in, p);
        }
        __syncthreads();
        __threadfence();
        if (threadIdx.x == 0) atomicExch(&g_flag[bid], 2);
    } else {
        // publish aggregate
        if (act) g_agg[row + f] = p;
        __syncthreads();
        __threadfence();
        if (threadIdx.x == 0) atomicExch(&g_flag[bid], 1);

        // decoupled lookback: s_in = sum_k aLL^k * X[c-1-k], terminated at a prefix
        float run = 0.0f;
        float sc  = 1.0f;
        int k = bid - B;                 // predecessor: same b, chunk c-1
        for (;;) {
            int fl = 0;
            if (lane == 0) {
                volatile int* vf = &g_flag[k];
                while ((fl = *vf) == 0) __nanosleep(60);
            }
            fl = __shfl_sync(0xffffffffu, fl, 0);
            __threadfence();             // acquire: order data loads after flag load
            if (fl == 2) {
                if (act) run = fmaf(sc, __ldcg(&g_pref[(size_t)k * Fq + f]), run);
                break;
            }
            if (act) run = fmaf(sc, __ldcg(&g_agg[(size_t)k * Fq + f]), run);
            sc *= aLL;
            k -= B;
        }
        s_in = run;

        // publish our inclusive prefix ASAP to unblock successors
        if (act) g_pref[row + f] = fmaf(aLL, s_in, p);
        __syncthreads();
        __threadfence();
        if (threadIdx.x == 0) atomicExch(&g_flag[bid], 2);
    }

    // ---- replay recurrence from registers, write output ----
    if (act) {
        float2* yp = reinterpret_cast<float2*>(y) + base;
        float s = s_in;
        #pragma unroll
        for (int j = 0; j < L; ++j) {
            float r2 = fmaxf(fmaf(v[j].x, v[j].x, v[j].y * v[j].y), EPSC);
            s = fmaf(r2 * rsqrtf(r2), OMA, s * AL);
            float scale = rsqrtf(s);
            float2 o;
            o.x = v[j].x * scale;
            o.y = v[j].y * scale;
            yp[(size_t)j * Fq] = o;
        }
    }
}

extern "C" void kernel_launch(void* const* d_in, const int* in_sizes, int n_in,
                              void* d_out, int out_size) {
    const float* x    = (const float*)d_in[0];
    const float* init = (const float*)d_in[1];
    if (n_in >= 2 && in_sizes[0] == Fq) {   // defensive: swapped order
        x    = (const float*)d_in[1];
        init = (const float*)d_in[0];
    }
    float* y = (float*)d_out;

    const float aLL = (float)pow((double)AL, (double)L);  // alpha^L

    // flags persist across graph replays -> must clear every launch
    void* flag_ptr = nullptr;
    cudaGetSymbolAddress(&flag_ptr, g_flag);
    cudaMemsetAsync(flag_ptr, 0, B * NC * sizeof(int));

    k_scan<<<B * NC, 512>>>(x, init, y, aLL);
}

// round 8
// speedup vs baseline: 1.1141x; 1.1141x over previous
#include <cuda_runtime.h>
#include <math.h>

// ExponentialUnitNorm: y = x / sqrt(s_t), s_t = 0.01*|x_t| + 0.99*s_{t-1}
// x [B=16, T=2000, F=481, 2] f32, init_state [F] f32.
//
// 3-pass exact chunked scan, tuned for L2 reuse:
//   pass 1: per (b,c,f) chunk partial (recurrence from 0); x read with .cg
//           so lines stay L2-resident (x = 117.4 MiB vs ~126 MB L2)
//   pass 2: tiny combine chaining incoming states: s[c+1] = a^L s[c] + P[c]
//   pass 3: replay recurrence in REVERSE block order (freshest L2 lines first);
//           x read with .cs (last touch, evict-first), y written with .cs
//           streaming stores so output never evicts x.

namespace {
constexpr int B  = 16;
constexpr int T  = 2000;
constexpr int Fq = 481;
constexpr int NC = 50;          // chunks over T
constexpr int L  = T / NC;      // 40
constexpr float AL   = 0.99f;
constexpr float OMA  = 0.01f;
constexpr float EPSC = 1e-14f;
constexpr int UN = 8;           // load prefetch depth
}

__device__ float g_P[B * NC * Fq];   // chunk partials
__device__ float g_S[B * NC * Fq];   // incoming state per chunk

__global__ __launch_bounds__(512) void k_partial(const float* __restrict__ x) {
    const int f = threadIdx.x;
    if (f >= Fq) return;
    const int c = blockIdx.x;
    const int b = blockIdx.y;
    const float2* xp = reinterpret_cast<const float2*>(x)
                       + (size_t)(b * T + c * L) * Fq + f;
    float p = 0.0f;
    #pragma unroll 1
    for (int i = 0; i < L; i += UN) {
        float2 v[UN];
        #pragma unroll
        for (int j = 0; j < UN; ++j) v[j] = __ldcg(&xp[(size_t)(i + j) * Fq]);
        #pragma unroll
        for (int j = 0; j < UN; ++j) {
            float r2  = fmaxf(fmaf(v[j].x, v[j].x, v[j].y * v[j].y), EPSC);
            p = fmaf(r2 * rsqrtf(r2), OMA, p * AL);
        }
    }
    g_P[((size_t)b * NC + c) * Fq + f] = p;
}

__global__ void k_combine(const float* __restrict__ init_state, float aL) {
    const int idx = blockIdx.x * blockDim.x + threadIdx.x;
    if (idx >= B * Fq) return;
    const int b = idx / Fq;
    const int f = idx - b * Fq;
    float s = init_state[f];
    #pragma unroll
    for (int c = 0; c < NC; ++c) {
        const size_t o = ((size_t)b * NC + c) * Fq + f;
        g_S[o] = s;
        s = fmaf(aL, s, g_P[o]);
    }
}

__global__ __launch_bounds__(512) void k_apply(const float* __restrict__ x,
                                               float* __restrict__ y) {
    const int f = threadIdx.x;
    if (f >= Fq) return;
    // Reverse dispatch order vs pass 1: freshest L2 lines get read first.
    const int c = (NC - 1) - blockIdx.x;
    const int b = (B  - 1) - blockIdx.y;
    const size_t base = (size_t)(b * T + c * L) * Fq + f;
    const float2* xp = reinterpret_cast<const float2*>(x) + base;
    float2*       yp = reinterpret_cast<float2*>(y) + base;
    float s = g_S[((size_t)b * NC + c) * Fq + f];
    #pragma unroll 1
    for (int i = 0; i < L; i += UN) {
        float2 v[UN];
        #pragma unroll
        for (int j = 0; j < UN; ++j)
            v[j] = __ldcs(&xp[(size_t)(i + j) * Fq]);   // last touch: evict-first
        #pragma unroll
        for (int j = 0; j < UN; ++j) {
            float r2  = fmaxf(fmaf(v[j].x, v[j].x, v[j].y * v[j].y), EPSC);
            s = fmaf(r2 * rsqrtf(r2), OMA, s * AL);
            float sc = rsqrtf(s);
            v[j].x *= sc;
            v[j].y *= sc;
        }
        #pragma unroll
        for (int j = 0; j < UN; ++j)
            __stcs(&yp[(size_t)(i + j) * Fq], v[j]);    // streaming: don't evict x
    }
}

extern "C" void kernel_launch(void* const* d_in, const int* in_sizes, int n_in,
                              void* d_out, int out_size) {
    const float* x    = (const float*)d_in[0];
    const float* init = (const float*)d_in[1];
    if (n_in >= 2 && in_sizes[0] == Fq) {   // defensive: swapped order
        x    = (const float*)d_in[1];
        init = (const float*)d_in[0];
    }
    float* y = (float*)d_out;

    const float aL = (float)pow((double)AL, (double)L);  // alpha^L

    dim3 grid(NC, B);
    k_partial<<<grid, 512>>>(x);
    k_combine<<<(B * Fq + 255) / 256, 256>>>(init, aL);
    k_apply<<<grid, 512>>>(x, y);
}

// round 11
// speedup vs baseline: 1.1620x; 1.0430x over previous
#include <cuda_runtime.h>
#include <math.h>

// ExponentialUnitNorm, single-pass decoupled-lookback scan, batched lookback.
// y = x / sqrt(s_t), s_t = 0.01*|x_t| + 0.99*s_{t-1}
// x [B=16, T=2000, F=481, 2] f32; init_state [F] f32.
//
// Chunked affine recurrence: s_end(c) = P(c) + aLL * s_end(c-1), aLL = 0.99^L.
// Block (b,c) holds its L=16 timesteps in SMEM across the lookback, so x is
// read from DRAM exactly once: total traffic = 123MB read + 123MB write.
// Lookback is batched 8 links at a time: one flag-batch poll + 8 independent
// aggregate loads per round (R3's one-link-per-roundtrip loop was the killer).

namespace {
constexpr int B  = 16;
constexpr int T  = 2000;
constexpr int Fq = 481;
constexpr int L  = 16;           // timesteps per chunk (SMEM resident)
constexpr int NC = T / L;        // 125 chunks
constexpr int LB = 8;            // lookback batch width
constexpr float AL   = 0.99f;
constexpr float OMA  = 0.01f;
constexpr float EPSC = 1e-14f;
constexpr int SMEM_BYTES = Fq * L * (int)sizeof(float2);  // 61,568 B
}

__device__ float g_agg [B * NC * Fq];   // chunk aggregates (recurrence from 0)
__device__ float g_pref[B * NC * Fq];   // inclusive prefix (state at chunk end)
__device__ int   g_flag[B * NC];        // [b][c]: 0 none, 1 aggregate, 2 prefix

__global__ __launch_bounds__(512, 2) void k_scan(const float* __restrict__ x,
                                                 const float* __restrict__ init_state,
                                                 float* __restrict__ y,
                                                 float aLL) {
    extern __shared__ float2 vs[];       // [L][Fq], f contiguous -> conflict-free
    const int bid = blockIdx.x;          // bid = c*B + b (chunk-major)
    const int c   = bid / B;
    const int b   = bid - c * B;
    const int f   = threadIdx.x;
    const bool act = (f < Fq);
    const int lane = threadIdx.x & 31;

    const size_t base = (size_t)(b * T + c * L) * Fq + f;

    // ---- load chunk -> SMEM, compute aggregate on the fly ----
    float p = 0.0f;
    if (act) {
        const float2* xp = reinterpret_cast<const float2*>(x) + base;
        #pragma unroll
        for (int j = 0; j < L; ++j) {
            float2 v = __ldcs(&xp[(size_t)j * Fq]);    // last gmem touch of x
            vs[j * Fq + f] = v;
            float r2 = fmaxf(fmaf(v.x, v.x, v.y * v.y), EPSC);
            p = fmaf(r2 * rsqrtf(r2), OMA, p * AL);
        }
    }

    const size_t rowcf = ((size_t)b * NC + c) * Fq;
    int* flagrow = &g_flag[b * NC];
    float s_in = 0.0f;

    if (c == 0) {
        if (act) {
            s_in = init_state[f];
            g_pref[rowcf + f] = fmaf(aLL, s_in, p);
        }
        __syncthreads();
        __threadfence();
        if (threadIdx.x == 0) atomicExch(&flagrow[0], 2);
    } else {
        // publish aggregate first so successors can proceed
        if (act) g_agg[rowcf + f] = p;
        __syncthreads();
        __threadfence();
        if (threadIdx.x == 0) atomicExch(&flagrow[c], 1);

        // ---- batched decoupled lookback ----
        float run = 0.0f;
        float sc  = 1.0f;
        int c0 = c - 1;                   // top predecessor of current batch
        for (;;) {
            int m = LB;                   // index of first prefix in batch, or LB
            if (lane == 0) {
                for (;;) {
                    int fl[LB];
                    #pragma unroll
                    for (int i = 0; i < LB; ++i) {
                        int j = c0 - i;
                        fl[i] = (j >= 0) ? __ldcg(&flagrow[j]) : 2;
                    }
                    int mm = LB;
                    bool retry = false;
                    #pragma unroll
                    for (int i = 0; i < LB; ++i) {
                        if (mm == LB && !retry) {
                            if (fl[i] == 2)      mm = i;
                            else if (fl[i] == 0) retry = true;
                        }
                    }
                    if (!retry) { m = mm; break; }
                    __nanosleep(40);
                }
            }
            m = __shfl_sync(0xffffffffu, m, 0);
            __threadfence();              // acquire: data loads after flag loads
            if (act) {
                #pragma unroll
                for (int i = 0; i < LB; ++i) {
                    if (i < m) {          // independent loads, MLP-batched
                        run = fmaf(sc, __ldcg(&g_agg[((size_t)b * NC + (c0 - i)) * Fq + f]), run);
                        sc *= aLL;
                    }
                }
                if (m < LB)
                    run = fmaf(sc, __ldcg(&g_pref[((size_t)b * NC + (c0 - m)) * Fq + f]), run);
            }
            if (m < LB) break;
            c0 -= LB;
        }
        s_in = run;

        // publish inclusive prefix ASAP
        if (act) g_pref[rowcf + f] = fmaf(aLL, s_in, p);
        __syncthreads();
        __threadfence();
        if (threadIdx.x == 0) atomicExch(&flagrow[c], 2);
    }

    // ---- replay recurrence from SMEM, write output ----
    if (act) {
        float2* yp = reinterpret_cast<float2*>(y) + base;
        float s = s_in;
        #pragma unroll
        for (int j = 0; j < L; ++j) {
            float2 v = vs[j * Fq + f];
            float r2 = fmaxf(fmaf(v.x, v.x, v.y * v.y), EPSC);
            s = fmaf(r2 * rsqrtf(r2), OMA, s * AL);
            float scale = rsqrtf(s);
            float2 o;
            o.x = v.x * scale;
            o.y = v.y * scale;
            __stcs(&yp[(size_t)j * Fq], o);
        }
    }
}

extern "C" void kernel_launch(void* const* d_in, const int* in_sizes, int n_in,
                              void* d_out, int out_size) {
    const float* x    = (const float*)d_in[0];
    const float* init = (const float*)d_in[1];
    if (n_in >= 2 && in_sizes[0] == Fq) {   // defensive: swapped order
        x    = (const float*)d_in[1];
        init = (const float*)d_in[0];
    }
    float* y = (float*)d_out;

    const float aLL = (float)pow((double)AL, (double)L);  // alpha^L

    // allow >48KB dynamic smem (host-side attribute set; not a stream op)
    cudaFuncSetAttribute(k_scan, cudaFuncAttributeMaxDynamicSharedMemorySize,
                         SMEM_BYTES);

    // flags persist across graph replays -> clear every launch
    void* flag_ptr = nullptr;
    cudaGetSymbolAddress(&flag_ptr, g_flag);
    cudaMemsetAsync(flag_ptr, 0, B * NC * sizeof(int));

    k_scan<<<B * NC, 512, SMEM_BYTES>>>(x, init, y, aLL);
}

// round 13
// speedup vs baseline: 1.2636x; 1.0874x over previous
#include <cuda_runtime.h>
#include <math.h>

// ExponentialUnitNorm, single-pass decoupled-lookback scan.
// y = x / sqrt(s_t), s_t = 0.01*|x_t| + 0.99*s_{t-1}
// x [B=16, T=2000, F=481, 2] f32; init_state [F] f32.
//
// Chunked affine recurrence: s_end(c) = P(c) + aLL * s_end(c-1), aLL = 0.99^L.
// Block (b,c) holds its L=25 timesteps in SMEM (96.2KB) across the lookback,
// so x is read from DRAM exactly once (246MB total traffic). L=25 (vs 16)
// raises on-chip data per wave 18.2MB -> 28.5MB => 6.8 -> 4.3 waves, and cuts
// lookback/fence events 125 -> 80 per chain. Lookback batched 8 links/round.

namespace {
constexpr int B  = 16;
constexpr int T  = 2000;
constexpr int Fq = 481;
constexpr int L  = 25;           // timesteps per chunk (SMEM resident)
constexpr int NC = T / L;        // 80 chunks
constexpr int LB = 8;            // lookback batch width
constexpr int UN = 5;            // load prefetch batch
constexpr float AL   = 0.99f;
constexpr float OMA  = 0.01f;
constexpr float EPSC = 1e-14f;
constexpr int SMEM_BYTES = Fq * L * (int)sizeof(float2);  // 96,200 B
}

__device__ float g_agg [B * NC * Fq];   // chunk aggregates (recurrence from 0)
__device__ float g_pref[B * NC * Fq];   // inclusive prefix (state at chunk end)
__device__ int   g_flag[B * NC];        // [b][c]: 0 none, 1 aggregate, 2 prefix

__global__ __launch_bounds__(512, 2) void k_scan(const float* __restrict__ x,
                                                 const float* __restrict__ init_state,
                                                 float* __restrict__ y,
                                                 float aLL) {
    extern __shared__ float2 vs[];       // [L][Fq], f contiguous -> conflict-free
    const int bid = blockIdx.x;          // bid = c*B + b (chunk-major)
    const int c   = bid / B;
    const int b   = bid - c * B;
    const int f   = threadIdx.x;
    const bool act = (f < Fq);
    const int lane = threadIdx.x & 31;

    const size_t base = (size_t)(b * T + c * L) * Fq + f;

    // ---- load chunk -> SMEM, compute aggregate on the fly ----
    float p = 0.0f;
    if (act) {
        const float2* xp = reinterpret_cast<const float2*>(x) + base;
        #pragma unroll 1
        for (int i = 0; i < L; i += UN) {
            float2 v[UN];
            #pragma unroll
            for (int j = 0; j < UN; ++j)
                v[j] = __ldcs(&xp[(size_t)(i + j) * Fq]);   // last gmem touch of x
            #pragma unroll
            for (int j = 0; j < UN; ++j) {
                vs[(i + j) * Fq + f] = v[j];
                float r2 = fmaxf(fmaf(v[j].x, v[j].x, v[j].y * v[j].y), EPSC);
                p = fmaf(r2 * rsqrtf(r2), OMA, p * AL);
            }
        }
    }

    const size_t rowcf = ((size_t)b * NC + c) * Fq;
    int* flagrow = &g_flag[b * NC];
    float s_in = 0.0f;

    if (c == 0) {
        if (act) {
            s_in = init_state[f];
            g_pref[rowcf + f] = fmaf(aLL, s_in, p);
        }
        __syncthreads();
        __threadfence();
        if (threadIdx.x == 0) atomicExch(&flagrow[0], 2);
    } else {
        // publish aggregate first so successors can proceed
        if (act) g_agg[rowcf + f] = p;
        __syncthreads();
        __threadfence();
        if (threadIdx.x == 0) atomicExch(&flagrow[c], 1);

        // ---- batched decoupled lookback ----
        float run = 0.0f;
        float sc  = 1.0f;
        int c0 = c - 1;                   // top predecessor of current batch
        for (;;) {
            int m = LB;                   // index of first prefix in batch, or LB
            if (lane == 0) {
                for (;;) {
                    int fl[LB];
                    #pragma unroll
                    for (int i = 0; i < LB; ++i) {
                        int j = c0 - i;
                        fl[i] = (j >= 0) ? __ldcg(&flagrow[j]) : 2;
                    }
                    int mm = LB;
                    bool retry = false;
                    #pragma unroll
                    for (int i = 0; i < LB; ++i) {
                        if (mm == LB && !retry) {
                            if (fl[i] == 2)      mm = i;
                            else if (fl[i] == 0) retry = true;
                        }
                    }
                    if (!retry) { m = mm; break; }
                    __nanosleep(40);
                }
            }
            m = __shfl_sync(0xffffffffu, m, 0);
            __threadfence();              // acquire: data loads after flag loads
            if (act) {
                #pragma unroll
                for (int i = 0; i < LB; ++i) {
                    if (i < m) {          // independent loads, MLP-batched
                        run = fmaf(sc, __ldcg(&g_agg[((size_t)b * NC + (c0 - i)) * Fq + f]), run);
                        sc *= aLL;
                    }
                }
                if (m < LB)
                    run = fmaf(sc, __ldcg(&g_pref[((size_t)b * NC + (c0 - m)) * Fq + f]), run);
            }
            if (m < LB) break;
            c0 -= LB;
        }
        s_in = run;

        // publish inclusive prefix ASAP
        if (act) g_pref[rowcf + f] = fmaf(aLL, s_in, p);
        __syncthreads();
        __threadfence();
        if (threadIdx.x == 0) atomicExch(&flagrow[c], 2);
    }

    // ---- replay recurrence from SMEM, write output ----
    if (act) {
        float2* yp = reinterpret_cast<float2*>(y) + base;
        float s = s_in;
        #pragma unroll 1
        for (int i = 0; i < L; i += UN) {
            #pragma unroll
            for (int j = 0; j < UN; ++j) {
                float2 v = vs[(i + j) * Fq + f];
                float r2 = fmaxf(fmaf(v.x, v.x, v.y * v.y), EPSC);
                s = fmaf(r2 * rsqrtf(r2), OMA, s * AL);
                float scale = rsqrtf(s);
                float2 o;
                o.x = v.x * scale;
                o.y = v.y * scale;
                __stcs(&yp[(size_t)(i + j) * Fq], o);
            }
        }
    }
}

extern "C" void kernel_launch(void* const* d_in, const int* in_sizes, int n_in,
                              void* d_out, int out_size) {
    const float* x    = (const float*)d_in[0];
    const float* init = (const float*)d_in[1];
    if (n_in >= 2 && in_sizes[0] == Fq) {   // defensive: swapped order
        x    = (const float*)d_in[1];
        init = (const float*)d_in[0];
    }
    float* y = (float*)d_out;

    const float aLL = (float)pow((double)AL, (double)L);  // alpha^L

    // allow >48KB dynamic smem (host-side attribute; not a stream op)
    cudaFuncSetAttribute(k_scan, cudaFuncAttributeMaxDynamicSharedMemorySize,
                         SMEM_BYTES);

    // flags persist across graph replays -> clear every launch
    void* flag_ptr = nullptr;
    cudaGetSymbolAddress(&flag_ptr, g_flag);
    cudaMemsetAsync(flag_ptr, 0, B * NC * sizeof(int));

    k_scan<<<B * NC, 512, SMEM_BYTES>>>(x, init, y, aLL);
}

// round 15
// speedup vs baseline: 1.3663x; 1.0814x over previous
#include <cuda_runtime.h>
#include <cstdint>
#include <math.h>

// ExponentialUnitNorm, single-pass decoupled-lookback scan.
// y = x / sqrt(s_t), s_t = 0.01*|x_t| + 0.99*s_{t-1}
// x [B=16, T=2000, F=481, 2] f32; init_state [F] f32.
//
// Chunked affine recurrence: s_end(c) = P(c) + aLL * s_end(c-1), aLL = 0.99^L.
// Block (b,c) holds its L=25 timesteps in SMEM (96.2KB, cp.async-loaded with
// 25-deep MLP) across the lookback, so x is read from DRAM exactly once
// (246MB total). Lookback batched 8 links/round. Flags are SELF-CLEANING:
// the last block of each row resets them, so no memset launch is needed and
// the graph is a single kernel node.

namespace {
constexpr int B  = 16;
constexpr int T  = 2000;
constexpr int Fq = 481;
constexpr int L  = 25;           // timesteps per chunk (SMEM resident)
constexpr int NC = T / L;        // 80 chunks
constexpr int LB = 8;            // lookback batch width
constexpr int UN = 5;            // replay unroll
constexpr float AL   = 0.99f;
constexpr float OMA  = 0.01f;
constexpr float EPSC = 1e-14f;
constexpr int SMEM_BYTES = Fq * L * (int)sizeof(float2);  // 96,200 B
}

__device__ float g_agg [B * NC * Fq];   // chunk aggregates (recurrence from 0)
__device__ float g_pref[B * NC * Fq];   // inclusive prefix (state at chunk end)
__device__ int   g_flag[B * NC];        // [b][c]: 0 none, 1 aggregate, 2 prefix

#define CP_ASYNC_8(dst_u32, src) \
    asm volatile("cp.async.ca.shared.global [%0], [%1], 8;\n" \
                 :: "r"(dst_u32), "l"(src))
#define CP_ASYNC_COMMIT()   asm volatile("cp.async.commit_group;\n")
#define CP_ASYNC_WAIT_ALL() asm volatile("cp.async.wait_all;\n" ::: "memory")

__global__ __launch_bounds__(512, 2) void k_scan(const float* __restrict__ x,
                                                 const float* __restrict__ init_state,
                                                 float* __restrict__ y,
                                                 float aLL) {
    extern __shared__ float2 vs[];       // [L][Fq]; each thread touches only col f
    const int bid = blockIdx.x;          // bid = c*B + b (chunk-major)
    const int c   = bid / B;
    const int b   = bid - c * B;
    const int f   = threadIdx.x;
    const bool act = (f < Fq);
    const int lane = threadIdx.x & 31;

    const size_t base = (size_t)(b * T + c * L) * Fq + f;

    // ---- async-load chunk -> SMEM with full-depth MLP (25 outstanding) ----
    if (act) {
        const float2* xp = reinterpret_cast<const float2*>(x) + base;
        unsigned int sdst = (unsigned int)__cvta_generic_to_shared(&vs[f]);
        #pragma unroll
        for (int j = 0; j < L; ++j)
            CP_ASYNC_8(sdst + (unsigned int)(j * Fq * sizeof(float2)),
                       &xp[(size_t)j * Fq]);
        CP_ASYNC_COMMIT();
    }

    // (no cross-thread SMEM sharing: each thread reads back only its own column,
    //  so a thread-local wait_all suffices — no __syncthreads needed here)
    float p = 0.0f;
    if (act) {
        CP_ASYNC_WAIT_ALL();
        #pragma unroll
        for (int j = 0; j < L; ++j) {
            float2 v = vs[j * Fq + f];
            float r2 = fmaxf(fmaf(v.x, v.x, v.y * v.y), EPSC);
            p = fmaf(r2 * rsqrtf(r2), OMA, p * AL);
        }
    }

    const size_t rowcf = ((size_t)b * NC + c) * Fq;
    int* flagrow = &g_flag[b * NC];
    float s_in = 0.0f;

    if (c == 0) {
        if (act) {
            s_in = init_state[f];
            g_pref[rowcf + f] = fmaf(aLL, s_in, p);
        }
        __syncthreads();
        __threadfence();
        if (threadIdx.x == 0) atomicExch(&flagrow[0], 2);
    } else {
        // publish aggregate first so successors can proceed
        if (act) g_agg[rowcf + f] = p;
        __syncthreads();
        __threadfence();
        if (threadIdx.x == 0) atomicExch(&flagrow[c], 1);

        // ---- batched decoupled lookback ----
        float run = 0.0f;
        float sc  = 1.0f;
        int c0 = c - 1;                   // top predecessor of current batch
        for (;;) {
            int m = LB;                   // index of first prefix in batch, or LB
            if (lane == 0) {
                for (;;) {
                    int fl[LB];
                    #pragma unroll
                    for (int i = 0; i < LB; ++i) {
                        int j = c0 - i;
                        fl[i] = (j >= 0) ? __ldcg(&flagrow[j]) : 2;
                    }
                    int mm = LB;
                    bool retry = false;
                    #pragma unroll
                    for (int i = 0; i < LB; ++i) {
                        if (mm == LB && !retry) {
                            if (fl[i] == 2)      mm = i;
                            else if (fl[i] == 0) retry = true;
                        }
                    }
                    if (!retry) { m = mm; break; }
                    __nanosleep(40);
                }
            }
            m = __shfl_sync(0xffffffffu, m, 0);
            __threadfence();              // acquire: data loads after flag loads
            if (act) {
                #pragma unroll
                for (int i = 0; i < LB; ++i) {
                    if (i < m) {          // independent loads, MLP-batched
                        run = fmaf(sc, __ldcg(&g_agg[((size_t)b * NC + (c0 - i)) * Fq + f]), run);
                        sc *= aLL;
                    }
                }
                if (m < LB)
                    run = fmaf(sc, __ldcg(&g_pref[((size_t)b * NC + (c0 - m)) * Fq + f]), run);
            }
            if (m < LB) break;
            c0 -= LB;
        }
        s_in = run;

        // publish inclusive prefix ASAP
        if (act) g_pref[rowcf + f] = fmaf(aLL, s_in, p);
        __syncthreads();
        __threadfence();
        if (threadIdx.x == 0) atomicExch(&flagrow[c], 2);
    }

    // ---- replay recurrence from SMEM, write output ----
    if (act) {
        float2* yp = reinterpret_cast<float2*>(y) + base;
        float s = s_in;
        #pragma unroll 1
        for (int i = 0; i < L; i += UN) {
            #pragma unroll
            for (int j = 0; j < UN; ++j) {
                float2 v = vs[(i + j) * Fq + f];
                float r2 = fmaxf(fmaf(v.x, v.x, v.y * v.y), EPSC);
                s = fmaf(r2 * rsqrtf(r2), OMA, s * AL);
                float scale = rsqrtf(s);
                float2 o;
                o.x = v.x * scale;
                o.y = v.y * scale;
                __stcs(&yp[(size_t)(i + j) * Fq], o);
            }
        }
    }

    // ---- self-cleaning flags: last block of each row resets its row to 0 ----
    // Every flag in the row is eventually set to 2 exactly once by its owner;
    // poll-then-clear in parallel (one flag per thread), so the next launch
    // (graph replay) starts from all-zero without a memset node.
    if (c == NC - 1 && threadIdx.x < NC) {
        volatile int* vf = &flagrow[threadIdx.x];
        while (*vf != 2) __nanosleep(40);
        *vf = 0;
    }
}

extern "C" void kernel_launch(void* const* d_in, const int* in_sizes, int n_in,
                              void* d_out, int out_size) {
    const float* x    = (const float*)d_in[0];
    const float* init = (const float*)d_in[1];
    if (n_in >= 2 && in_sizes[0] == Fq) {   // defensive: swapped order
        x    = (const float*)d_in[1];
        init = (const float*)d_in[0];
    }
    float* y = (float*)d_out;

    const float aLL = (float)pow((double)AL, (double)L);  // alpha^L

    // allow >48KB dynamic smem (host-side attribute; not a stream op)
    cudaFuncSetAttribute(k_scan, cudaFuncAttributeMaxDynamicSharedMemorySize,
                         SMEM_BYTES);

    k_scan<<<B * NC, 512, SMEM_BYTES>>>(x, init, y, aLL);
}